// round 2
// baseline (speedup 1.0000x reference)
#include <cuda_runtime.h>
#include <math.h>

#define NIMG 512
#define IMG_ELEMS (64*64*32)   // 131072 floats per "image" (bg slice)

// ---- scratch (device globals; allocation-free rule) ----
__device__ float g_x2[67108864];        // 512 * 131072, conv output
__device__ float g_sh[NIMG*64*32];      // sigmoid(x_h)
__device__ float g_sw[NIMG*64*32];      // sigmoid(x_w)
__device__ float g_sum[NIMG*32];        // gated sum   (GN)
__device__ float g_sumsq[NIMG*32];      // gated sumsq (GN)
__device__ float g_colsum[NIMG*32];     // x2 channel sums (for x21 softmax)
__device__ float g_mu[NIMG*32];
__device__ float g_rs[NIMG*32];
__device__ float g_x21[NIMG*32];
__device__ float g_x11[32];

// ===================== K1: row/col means + 32x32 matmul + sigmoid =====================
__global__ void __launch_bounds__(256) k1_means(const float* __restrict__ x,
                                                const float* __restrict__ w1,
                                                const float* __restrict__ b1) {
    int g = blockIdx.x;
    const float* A = x + (size_t)g * IMG_ELEMS;
    __shared__ float s_xh[2048], s_xw[2048], s_w1[1024];
    int tid = threadIdx.x, lane = tid & 31, wid = tid >> 5;

    if (tid < 32) {  // zero atomic targets for this image (graph replays re-zero)
        g_sum[g*32+tid] = 0.f; g_sumsq[g*32+tid] = 0.f; g_colsum[g*32+tid] = 0.f;
    }
    for (int i = tid; i < 1024; i += 256) s_w1[i] = w1[i];

    // x_h: mean over w. warp = one h row, lane = channel (coalesced)
    for (int h = wid; h < 64; h += 8) {
        float acc = 0.f;
        #pragma unroll 8
        for (int w = 0; w < 64; w++) acc += A[(h*64 + w)*32 + lane];
        s_xh[h*32 + lane] = acc * (1.f/64.f);
    }
    // x_w: mean over h. warp = one w column (L2-resident second pass)
    for (int w = wid; w < 64; w += 8) {
        float acc = 0.f;
        #pragma unroll 8
        for (int h = 0; h < 64; h++) acc += A[(h*64 + w)*32 + lane];
        s_xw[w*32 + lane] = acc * (1.f/64.f);
    }
    __syncthreads();

    // 128 rows (64 h + 64 w) x 32 outputs; sigmoid; store
    for (int i = tid; i < 4096; i += 256) {
        int row = i >> 5, d = i & 31;
        const float* v = (row < 64) ? &s_xh[row*32] : &s_xw[(row-64)*32];
        float acc = b1[d];
        #pragma unroll
        for (int c = 0; c < 32; c++) acc = fmaf(v[c], s_w1[c*32 + d], acc);
        float s = 1.f / (1.f + expf(-acc));
        if (row < 64) g_sh[(g*64 + row)*32 + d] = s;
        else          g_sw[(g*64 + (row-64))*32 + d] = s;
    }
}

// ===================== K2: 3x3 conv (SAME) + colsum + gated GN stats =====================
// Tile: 4 output rows x 64 cols x 32ch per block. 8 warps; warp owns 32 pixels; lane = out channel d.
__global__ void __launch_bounds__(256) k2_conv(const float* __restrict__ x,
                                               const float* __restrict__ w3,
                                               const float* __restrict__ b3) {
    int g = blockIdx.y, tile = blockIdx.x, h0 = tile * 4;
    const float* A = x + (size_t)g * IMG_ELEMS;
    extern __shared__ float sm[];
    float* s_w   = sm;              // 9216  : w3[kh][kw][ci][d]
    float* s_in  = sm + 9216;       // 6*66*32 = 12672 : halo tile, zero-padded cols 0/65
    float* s_red = s_in + 12672;    // 3*8*32 = 768
    int tid = threadIdx.x, lane = tid & 31, wid = tid >> 5;

    for (int i = tid; i < 9216; i += 256) s_w[i] = w3[i];
    for (int i = tid; i < (6*66*32)/4; i += 256) {
        int idx = i * 4;
        int r   = idx / (66*32);
        int rem = idx - r * (66*32);
        int col = rem >> 5;
        int ci  = rem & 31;
        float4 v = make_float4(0.f, 0.f, 0.f, 0.f);
        int h = h0 - 1 + r;
        if (col >= 1 && col <= 64 && h >= 0 && h < 64)
            v = *(const float4*)&A[(h*64 + (col-1))*32 + ci];
        *(float4*)&s_in[idx] = v;
    }
    __syncthreads();

    float acc[32];
    #pragma unroll
    for (int j = 0; j < 32; j++) acc[j] = 0.f;
    int hl = wid >> 1, wbase = (wid & 1) * 32;

    for (int c0 = 0; c0 < 32; c0 += 4) {       // ci chunks of 4
        float wr[9][4];
        #pragma unroll
        for (int k = 0; k < 9; k++)
            #pragma unroll
            for (int j = 0; j < 4; j++) wr[k][j] = s_w[k*1024 + (c0+j)*32 + lane];
        #pragma unroll
        for (int j2 = 0; j2 < 32; j2++) {       // pixels: 1 LDS.128 broadcast per 4 FFMA
            int wq = wbase + j2;
            float a = acc[j2];
            #pragma unroll
            for (int kh = 0; kh < 3; kh++)
                #pragma unroll
                for (int kw = 0; kw < 3; kw++) {
                    const float4 a4 = *(const float4*)&s_in[((hl+kh)*66 + (wq+kw))*32 + c0];
                    int k = kh*3 + kw;
                    a = fmaf(a4.x, wr[k][0], a);
                    a = fmaf(a4.y, wr[k][1], a);
                    a = fmaf(a4.z, wr[k][2], a);
                    a = fmaf(a4.w, wr[k][3], a);
                }
            acc[j2] = a;
        }
    }

    // write x2 (+b3) and per-warp channel sums
    float b3v = b3[lane];
    float csum = 0.f;
    int h = h0 + hl;
    #pragma unroll
    for (int j2 = 0; j2 < 32; j2++) {
        float v = acc[j2] + b3v;
        g_x2[((size_t)g*4096 + h*64 + wbase + j2)*32 + lane] = v;
        csum += v;
    }

    // gated GN stats from the same smem tile (lane = channel)
    float shv = g_sh[(g*64 + h)*32 + lane];
    float s1 = 0.f, s2 = 0.f;
    #pragma unroll
    for (int j2 = 0; j2 < 32; j2++) {
        int wq = wbase + j2;
        float a  = s_in[((hl+1)*66 + (wq+1))*32 + lane];
        float gt = a * shv * g_sw[(g*64 + wq)*32 + lane];
        s1 += gt; s2 += gt*gt;
    }
    s_red[(0*8 + wid)*32 + lane] = csum;
    s_red[(1*8 + wid)*32 + lane] = s1;
    s_red[(2*8 + wid)*32 + lane] = s2;
    __syncthreads();
    if (wid < 3) {
        float t = 0.f;
        #pragma unroll
        for (int k = 0; k < 8; k++) t += s_red[(wid*8 + k)*32 + lane];
        float* dst = (wid == 0) ? g_colsum : (wid == 1) ? g_sum : g_sumsq;
        atomicAdd(&dst[g*32 + lane], t);
    }
}

// ===================== K3: mu/rsqrt, softmax(x21), softmax(gn_beta)=x11 =====================
__global__ void k3_finalize(const float* __restrict__ gn_beta) {
    int g = blockIdx.x, t = threadIdx.x;
    float mu  = g_sum[g*32 + t] * (1.f/4096.f);
    float var = g_sumsq[g*32 + t] * (1.f/4096.f) - mu*mu;
    g_mu[g*32 + t] = mu;
    g_rs[g*32 + t] = rsqrtf(var + 1e-3f);

    float m = g_colsum[g*32 + t] * (1.f/4096.f);
    float mx = m;
    #pragma unroll
    for (int o = 16; o > 0; o >>= 1) mx = fmaxf(mx, __shfl_xor_sync(0xffffffffu, mx, o));
    float e = expf(m - mx);
    float se = e;
    #pragma unroll
    for (int o = 16; o > 0; o >>= 1) se += __shfl_xor_sync(0xffffffffu, se, o);
    g_x21[g*32 + t] = e / se;

    if (g == 0) {  // x11 = softmax(mean(x1)) = softmax(gn_beta), same for all images
        float bb = gn_beta[t];
        float mx2 = bb;
        #pragma unroll
        for (int o = 16; o > 0; o >>= 1) mx2 = fmaxf(mx2, __shfl_xor_sync(0xffffffffu, mx2, o));
        float e2 = expf(bb - mx2);
        float s2 = e2;
        #pragma unroll
        for (int o = 16; o > 0; o >>= 1) s2 += __shfl_xor_sync(0xffffffffu, s2, o);
        g_x11[t] = e2 / s2;
    }
}

// ===================== K4: weights (flat einsum) + sigmoid + output =====================
__global__ void __launch_bounds__(1024) k4_weights_out(const float* __restrict__ x,
                                                       const float* __restrict__ gn_gamma,
                                                       const float* __restrict__ gn_beta,
                                                       float* __restrict__ out) {
    int g = blockIdx.x, tid = threadIdx.x;
    const float* A  = x    + (size_t)g * IMG_ELEMS;
    const float* X2 = g_x2 + (size_t)g * IMG_ELEMS;
    __shared__ float s_wt[4096];
    __shared__ float s_sh[2048], s_sw[2048];
    __shared__ float s_x11[32], s_x21[32], s_mu[32], s_rs[32], s_gb[64];
    // FIX (R1 bug): tables have 2048 entries but blockDim is 1024 — must stride.
    for (int i = tid; i < 2048; i += 1024) {
        s_sh[i] = g_sh[g*2048 + i];
        s_sw[i] = g_sw[g*2048 + i];
    }
    if (tid < 32) {
        s_x11[tid] = g_x11[tid];
        s_x21[tid] = g_x21[g*32 + tid];
        s_mu[tid]  = g_mu[g*32 + tid];
        s_rs[tid]  = g_rs[g*32 + tid];
        s_gb[tid]      = gn_gamma[tid];
        s_gb[32 + tid] = gn_beta[tid];
    }
    __syncthreads();

    // weights[l] = sum_c x11[c]*x2flat[c*4096+l] + x21[c]*x1flat[c*4096+l]
    // x1flat recomputed from A on the fly. Fully coalesced (lane <-> l).
    #pragma unroll
    for (int k = 0; k < 4; k++) {
        int l  = tid + k*1024;
        int cc = l & 31;
        int q  = l >> 5;          // 0..127
        int w  = q & 63;
        float rs = s_rs[cc], mu = s_mu[cc], gam = s_gb[cc], bet = s_gb[32 + cc];
        float swv = s_sw[w*32 + cc];
        float acc = 0.f;
        #pragma unroll 8
        for (int c = 0; c < 32; c++) {
            int f = c*4096 + l;
            float x2v = X2[f];
            float a   = A[f];
            int h = 2*c + (q >> 6);
            float gt  = a * s_sh[h*32 + cc] * swv;
            float x1v = (gt - mu) * rs * gam + bet;
            acc += s_x11[c]*x2v + s_x21[c]*x1v;
        }
        s_wt[l] = 1.f / (1.f + expf(-acc));   // sigmoid(weights)
    }
    __syncthreads();

    // out = gx * sigmoid(weights)  (weights broadcast over 32 channels)
    const float4* A4 = (const float4*)A;
    float4* O4 = (float4*)(out + (size_t)g * IMG_ELEMS);
    for (int i = tid; i < IMG_ELEMS/4; i += 1024) {
        float sg = s_wt[i >> 3];   // (i*4) >> 5
        float4 a4 = A4[i];
        float4 o;
        o.x = a4.x*sg; o.y = a4.y*sg; o.z = a4.z*sg; o.w = a4.w*sg;
        O4[i] = o;
    }
}

// ===================== launch =====================
extern "C" void kernel_launch(void* const* d_in, const int* in_sizes, int n_in,
                              void* d_out, int out_size) {
    const float* x     = (const float*)d_in[0];
    const float* w1    = (const float*)d_in[1];
    const float* b1    = (const float*)d_in[2];
    const float* w3    = (const float*)d_in[3];
    const float* b3    = (const float*)d_in[4];
    const float* gamma = (const float*)d_in[5];
    const float* beta  = (const float*)d_in[6];
    float* out = (float*)d_out;

    const int k2_smem = (9216 + 12672 + 768) * 4;   // 90624 B
    cudaFuncSetAttribute(k2_conv, cudaFuncAttributeMaxDynamicSharedMemorySize, k2_smem);

    k1_means<<<NIMG, 256>>>(x, w1, b1);
    k2_conv<<<dim3(16, NIMG), 256, k2_smem>>>(x, w3, b3);
    k3_finalize<<<NIMG, 32>>>(beta);
    k4_weights_out<<<NIMG, 1024>>>(x, gamma, beta, out);
}